// round 6
// baseline (speedup 1.0000x reference)
#include <cuda_runtime.h>
#include <math.h>
#include <stdint.h>
#include <mma.h>

using namespace nvcuda;

#define B_   4
#define C_   2048
#define D_   1024
#define H_   16
#define HD_  64
#define KS_  512
#define STRIDE_ 4
#define EPS_ 1.1920929e-07f

// ---------------- scratch (device globals) -----------------------------------
__device__ float g_xqn [B_*C_*D_];
__device__ float g_xkvn[B_*KS_*D_];
__device__ float g_q   [B_*C_*D_];
__device__ float g_kv  [B_*KS_*2*D_];
__device__ float g_qn  [B_*H_*C_*HD_];    // tf32, pre-scaled by 0.125
__device__ float g_kn  [B_*H_*KS_*HD_];   // tf32
__device__ float g_v   [B_*H_*KS_*HD_];   // tf32
__device__ float g_attn[B_*C_*D_];        // tf32
__device__ float g_wq  [D_*D_];
__device__ float g_wkv [D_*2*D_];
__device__ float g_wo  [D_*D_];
__device__ float g_base[HD_/2];
__device__ float2 g_trig[C_*32];          // (cos, sin) per (t, freq)

__device__ __forceinline__ float to_tf32(float x) {
    float r; asm("cvt.rna.tf32.f32 %0, %1;" : "=f"(r) : "f"(x)); return r;
}
__device__ __forceinline__ uint32_t smem_u32(const void* p) {
    uint32_t a;
    asm("{ .reg .u64 t; cvta.to.shared.u64 t, %1; cvt.u32.u64 %0, t; }"
        : "=r"(a) : "l"(p));
    return a;
}
__device__ __forceinline__ void cp16(uint32_t dst, const void* src) {
    asm volatile("cp.async.cg.shared.global [%0], [%1], 16;" :: "r"(dst), "l"(src));
}
#define CP_COMMIT() asm volatile("cp.async.commit_group;" ::: "memory")
#define CP_WAIT1()  asm volatile("cp.async.wait_group 1;" ::: "memory")
#define CP_WAIT0()  asm volatile("cp.async.wait_group 0;" ::: "memory")

// =================== wmma tf32 GEMM (3-stage cp.async pipeline) ================
// 128x128 CTA tile, K-chunk 32, 8 warps (2m x 4n), warp tile 64x32.
#define GA_LD 36
#define GB_LD 140
#define EP_LD 36
__global__ __launch_bounds__(256, 2) void gemm_wmma_kernel(
        const float* __restrict__ A, const float* __restrict__ W,
        const float* __restrict__ bias, float* __restrict__ C,
        int M, int N, int K) {
    extern __shared__ float sm[];
    float* As = sm;                       // 3*128*36 = 13824 floats
    float* Bs = sm + 3 * 128 * GA_LD;     // 3*32*140 = 13440 floats
    uint32_t asu = smem_u32(As), bsu = smem_u32(Bs);

    int tid = threadIdx.x;
    int warp = tid >> 5;
    int lane = tid & 31;
    int wm = warp & 1;
    int wn = warp >> 1;
    int m0 = blockIdx.y * 128;
    int n0 = blockIdx.x * 128;
    int nc = K >> 5;

#define G_STAGE(cc, bb) do { \
    uint32_t abase = asu + (uint32_t)(bb) * (128 * GA_LD * 4); \
    _Pragma("unroll") \
    for (int i = 0; i < 4; i++) { \
        int u = tid + i * 256; int r = u >> 3, q = u & 7; \
        cp16(abase + (uint32_t)(r * GA_LD + q * 4) * 4, \
             A + (size_t)(m0 + r) * K + (cc) * 32 + q * 4); \
    } \
    uint32_t bbase = bsu + (uint32_t)(bb) * (32 * GB_LD * 4); \
    _Pragma("unroll") \
    for (int i = 0; i < 4; i++) { \
        int u = tid + i * 256; int r = u >> 5, q = u & 31; \
        cp16(bbase + (uint32_t)(r * GB_LD + q * 4) * 4, \
             W + (size_t)((cc) * 32 + r) * N + n0 + q * 4); \
    } \
    CP_COMMIT(); \
} while (0)

    wmma::fragment<wmma::accumulator, 16, 16, 8, float> acc[4][2];
#pragma unroll
    for (int i = 0; i < 4; i++)
#pragma unroll
        for (int j = 0; j < 2; j++) wmma::fill_fragment(acc[i][j], 0.0f);

    G_STAGE(0, 0);
    G_STAGE(1, 1);

    for (int c = 0; c < nc; c++) {
        if (c + 1 < nc) { CP_WAIT1(); } else { CP_WAIT0(); }
        __syncthreads();
        if (c + 2 < nc) G_STAGE(c + 2, (c + 2) % 3);
        const float* Ab = As + (c % 3) * (128 * GA_LD);
        const float* Bb = Bs + (c % 3) * (32 * GB_LD);
#pragma unroll
        for (int ks = 0; ks < 4; ks++) {
            wmma::fragment<wmma::matrix_a, 16, 16, 8, wmma::precision::tf32, wmma::row_major> af[4];
            wmma::fragment<wmma::matrix_b, 16, 16, 8, wmma::precision::tf32, wmma::row_major> bf[2];
#pragma unroll
            for (int i = 0; i < 4; i++)
                wmma::load_matrix_sync(af[i], Ab + (wm * 64 + i * 16) * GA_LD + ks * 8, GA_LD);
#pragma unroll
            for (int j = 0; j < 2; j++)
                wmma::load_matrix_sync(bf[j], Bb + (ks * 8) * GB_LD + wn * 32 + j * 16, GB_LD);
#pragma unroll
            for (int i = 0; i < 4; i++)
#pragma unroll
                for (int j = 0; j < 2; j++)
                    wmma::mma_sync(acc[i][j], af[i], bf[j], acc[i][j]);
        }
    }
    __syncthreads();   // before reusing sm for epilogue staging

    float* wsm = sm + warp * (64 * EP_LD);
#pragma unroll
    for (int i = 0; i < 4; i++)
#pragma unroll
        for (int j = 0; j < 2; j++)
            wmma::store_matrix_sync(wsm + (i * 16) * EP_LD + j * 16, acc[i][j], EP_LD,
                                    wmma::mem_row_major);
    __syncwarp();
#pragma unroll
    for (int r2 = 0; r2 < 2; r2++) {
        int r = r2 * 32 + lane;
        float* crow = C + (size_t)(m0 + wm * 64 + r) * N + n0 + wn * 32;
        const float* srow = wsm + r * EP_LD;
        const float* brow = bias + n0 + wn * 32;
#pragma unroll
        for (int q = 0; q < 8; q++) {
            float4 v;
            v.x = srow[q * 4 + 0] + brow[q * 4 + 0];
            v.y = srow[q * 4 + 1] + brow[q * 4 + 1];
            v.z = srow[q * 4 + 2] + brow[q * 4 + 2];
            v.w = srow[q * 4 + 3] + brow[q * 4 + 3];
            *(float4*)(crow + q * 4) = v;
        }
    }
#undef G_STAGE
}

// =================== fused wmma attention (512 thr, 3-stage, fast softmax) ====
#define AQ_LD 72
#define AS_LD 520
__global__ __launch_bounds__(512) void attention_wmma_kernel() {
    extern __shared__ float sm[];
    float* Qs   = sm;                      // 64*72    = 4608
    float* KVs  = sm + 4608;               // 3*64*72  = 13824
    float* Ss   = sm + 18432;              // 64*520   = 33280
    float* sinv = sm + 51712;              // 64
    uint32_t qsu = smem_u32(Qs), kvu = smem_u32(KVs);

    int tid = threadIdx.x;
    int warp = tid >> 5;
    int lane = tid & 31;
    int wm = warp & 3;
    int wn = warp >> 2;
    int bh = blockIdx.y;
    int qbase = blockIdx.x * 64;

    const float* qsrc = g_qn + ((size_t)bh * C_ + qbase) * HD_;
    const float* ksrc = g_kn + (size_t)bh * KS_ * HD_;
    const float* vsrc = g_v  + (size_t)bh * KS_ * HD_;

#define A_STAGE(src, ch, bb) do { \
    uint32_t base = kvu + (uint32_t)(bb) * (64 * AQ_LD * 4); \
    _Pragma("unroll") \
    for (int i = 0; i < 2; i++) { \
        int u = tid + i * 512; int r = u >> 4, q = u & 15; \
        cp16(base + (uint32_t)(r * AQ_LD + q * 4) * 4, \
             (src) + ((ch) * 64 + r) * HD_ + q * 4); \
    } \
    CP_COMMIT(); \
} while (0)

    // prologue: Q (with K chunk0 group), K chunk1
    {
#pragma unroll
        for (int i = 0; i < 2; i++) {
            int u = tid + i * 512; int r = u >> 4, q = u & 15;
            cp16(qsu + (uint32_t)(r * AQ_LD + q * 4) * 4, qsrc + r * HD_ + q * 4);
        }
#pragma unroll
        for (int i = 0; i < 2; i++) {
            int u = tid + i * 512; int r = u >> 4, q = u & 15;
            cp16(kvu + (uint32_t)(r * AQ_LD + q * 4) * 4, ksrc + r * HD_ + q * 4);
        }
        CP_COMMIT();
    }
    A_STAGE(ksrc, 1, 1);

    // ---- scores: S[64][512] = Q @ K^T (Q pre-scaled by 0.125) ----------------
    for (int ch = 0; ch < 8; ch++) {
        if (ch + 1 < 8) { CP_WAIT1(); } else { CP_WAIT0(); }
        __syncthreads();
        if (ch + 2 < 8) A_STAGE(ksrc, ch + 2, (ch + 2) % 3);
        const float* Kb = KVs + (ch % 3) * (64 * AQ_LD);
        wmma::fragment<wmma::accumulator, 16, 16, 8, float> sacc;
        wmma::fill_fragment(sacc, 0.0f);
#pragma unroll
        for (int ks = 0; ks < 8; ks++) {
            wmma::fragment<wmma::matrix_a, 16, 16, 8, wmma::precision::tf32, wmma::row_major> af;
            wmma::fragment<wmma::matrix_b, 16, 16, 8, wmma::precision::tf32, wmma::col_major> bf;
            wmma::load_matrix_sync(af, Qs + (wm * 16) * AQ_LD + ks * 8, AQ_LD);
            wmma::load_matrix_sync(bf, Kb + (wn * 16) * AQ_LD + ks * 8, AQ_LD);
            wmma::mma_sync(sacc, af, bf, sacc);
        }
        wmma::store_matrix_sync(Ss + (wm * 16) * AS_LD + ch * 64 + wn * 16,
                                sacc, AS_LD, wmma::mem_row_major);
    }
    __syncthreads();

    // prefetch V chunks 0,1 (overlaps softmax)
    A_STAGE(vsrc, 0, 0);
    A_STAGE(vsrc, 1, 1);

    // ---- softmax: no max-shift (|s|<=8), e in regs, 1/sum deferred to O ------
    for (int rr = 0; rr < 4; rr++) {
        int r = warp * 4 + rr;
        float4* row4 = (float4*)(Ss + r * AS_LD);
        float e[16]; float sum;
        float4 v0 = row4[lane];
        float4 v1 = row4[lane + 32];
        float4 v2 = row4[lane + 64];
        float4 v3 = row4[lane + 96];
        e[0]=__expf(v0.x); e[1]=__expf(v0.y); e[2]=__expf(v0.z); e[3]=__expf(v0.w);
        e[4]=__expf(v1.x); e[5]=__expf(v1.y); e[6]=__expf(v1.z); e[7]=__expf(v1.w);
        e[8]=__expf(v2.x); e[9]=__expf(v2.y); e[10]=__expf(v2.z); e[11]=__expf(v2.w);
        e[12]=__expf(v3.x); e[13]=__expf(v3.y); e[14]=__expf(v3.z); e[15]=__expf(v3.w);
        sum = ((e[0]+e[1])+(e[2]+e[3])) + ((e[4]+e[5])+(e[6]+e[7]))
            + ((e[8]+e[9])+(e[10]+e[11])) + ((e[12]+e[13])+(e[14]+e[15]));
#pragma unroll
        for (int o = 16; o; o >>= 1) sum += __shfl_xor_sync(0xffffffffu, sum, o);
        if (lane == 0) sinv[r] = 1.0f / sum;
        float4 w;
        w.x=to_tf32(e[0]);  w.y=to_tf32(e[1]);  w.z=to_tf32(e[2]);  w.w=to_tf32(e[3]);  row4[lane]      = w;
        w.x=to_tf32(e[4]);  w.y=to_tf32(e[5]);  w.z=to_tf32(e[6]);  w.w=to_tf32(e[7]);  row4[lane + 32] = w;
        w.x=to_tf32(e[8]);  w.y=to_tf32(e[9]);  w.z=to_tf32(e[10]); w.w=to_tf32(e[11]); row4[lane + 64] = w;
        w.x=to_tf32(e[12]); w.y=to_tf32(e[13]); w.z=to_tf32(e[14]); w.w=to_tf32(e[15]); row4[lane + 96] = w;
    }

    // ---- O = E @ V, then scale rows by sinv -----------------------------------
    wmma::fragment<wmma::accumulator, 16, 16, 8, float> oacc;
    wmma::fill_fragment(oacc, 0.0f);
    for (int ch = 0; ch < 8; ch++) {
        if (ch + 1 < 8) { CP_WAIT1(); } else { CP_WAIT0(); }
        __syncthreads();
        if (ch + 2 < 8) A_STAGE(vsrc, ch + 2, (ch + 2) % 3);
        const float* Vb = KVs + (ch % 3) * (64 * AQ_LD);
#pragma unroll
        for (int ks = 0; ks < 8; ks++) {
            wmma::fragment<wmma::matrix_a, 16, 16, 8, wmma::precision::tf32, wmma::row_major> af;
            wmma::fragment<wmma::matrix_b, 16, 16, 8, wmma::precision::tf32, wmma::row_major> bf;
            wmma::load_matrix_sync(af, Ss + (wm * 16) * AS_LD + ch * 64 + ks * 8, AS_LD);
            wmma::load_matrix_sync(bf, Vb + (ks * 8) * AQ_LD + wn * 16, AQ_LD);
            wmma::mma_sync(oacc, af, bf, oacc);
        }
    }

    // stage O tile in Qs (free), then scaled + tf32-rounded coalesced writes
    wmma::store_matrix_sync(Qs + (wm * 16) * AQ_LD + wn * 16, oacc, AQ_LD,
                            wmma::mem_row_major);
    __syncthreads();
    int b = bh >> 4, h = bh & 15;
#pragma unroll
    for (int i = 0; i < 2; i++) {
        int u = tid + i * 512;          // 0..1023
        int r = u >> 4;                 // q row 0..63
        int q = (u & 15) * 4;           // col 0..60
        float s = sinv[r];
        const float* src = Qs + r * AQ_LD + q;
        float4 w;
        w.x = to_tf32(src[0] * s);
        w.y = to_tf32(src[1] * s);
        w.z = to_tf32(src[2] * s);
        w.w = to_tf32(src[3] * s);
        *(float4*)(g_attn + ((size_t)b * C_ + qbase + r) * D_ + h * HD_ + q) = w;
    }
#undef A_STAGE
}

// ---------------- rope base + trig table ----------------------------------------
__global__ void init_base_kernel() {
    int i = threadIdx.x;
    double end = 2595.0 * log10(21.0);
    double v = (double)i * (end / 31.0);
    double scale = pow(10.0, v / 2595.0) - 1.0;
    g_base[i] = (float)(200.0 * scale / 1000.0);
}
__global__ void trig_kernel() {
    int c = blockIdx.x;                 // 0..2047
    int lane = threadIdx.x;             // 0..31
    float fr = (float)c * g_base[lane];
    float sn, cs; sincosf(fr, &sn, &cs);
    g_trig[c * 32 + lane] = make_float2(cs, sn);
}

// ---------------- weight tf32 conversion ----------------------------------------
__global__ void cvt_kernel(const float* __restrict__ s, float* __restrict__ d, int n4) {
    int i = blockIdx.x * 256 + threadIdx.x;
    if (i < n4) {
        float4 v = ((const float4*)s)[i];
        v.x = to_tf32(v.x); v.y = to_tf32(v.y);
        v.z = to_tf32(v.z); v.w = to_tf32(v.w);
        ((float4*)d)[i] = v;
    }
}

// ---------------- dual rmsnorm (tf32 outputs) ------------------------------------
__global__ void rmsnorm_dual_kernel(const float* __restrict__ x,
                                    const float* __restrict__ wq,
                                    const float* __restrict__ wkv) {
    int row = blockIdx.x;
    int tid = threadIdx.x;
    const float* xr = x + (size_t)row * D_;
    float v[4]; float ss = 0.f;
#pragma unroll
    for (int i = 0; i < 4; i++) { v[i] = xr[tid + i*256]; ss += v[i]*v[i]; }
#pragma unroll
    for (int o = 16; o; o >>= 1) ss += __shfl_xor_sync(0xffffffffu, ss, o);
    __shared__ float red[8];
    if ((tid & 31) == 0) red[tid >> 5] = ss;
    __syncthreads();
    float tot = 0.f;
#pragma unroll
    for (int i = 0; i < 8; i++) tot += red[i];
    float r = rsqrtf(tot * (1.f / D_) + EPS_);

    int b = row >> 11, c = row & (C_ - 1);
    bool dokv = (c & (STRIDE_ - 1)) == 0;
    int krow = b * KS_ + (c >> 2);
#pragma unroll
    for (int i = 0; i < 4; i++) {
        int col = tid + i*256;
        float n = v[i] * r;
        g_xqn[(size_t)row * D_ + col] = to_tf32(n * wq[col]);
        if (dokv) g_xkvn[(size_t)krow * D_ + col] = to_tf32(n * wkv[col]);
    }
}

// ---------------- rope + per-head rmsnorm on Q (table-based) ---------------------
__global__ void rope_norm_q_kernel(const float* __restrict__ ln_w) {
    int row = blockIdx.x;
    int h = threadIdx.x >> 5;
    int lane = threadIdx.x & 31;
    int b = row >> 11, c = row & (C_ - 1);
    const float* qp = g_q + (size_t)row * D_ + h * HD_;
    float a  = qp[2 * lane];
    float bb = qp[2 * lane + 1];
    float2 t = g_trig[c * 32 + lane];
    float na = a * t.x - bb * t.y;
    float nb = a * t.y + bb * t.x;
    float ss = na * na + nb * nb;
#pragma unroll
    for (int o = 16; o; o >>= 1) ss += __shfl_xor_sync(0xffffffffu, ss, o);
    float r = rsqrtf(ss * (1.f / HD_) + EPS_);
    size_t ob = (((size_t)(b * H_ + h) * C_) + c) * HD_ + 2 * lane;
    g_qn[ob]     = to_tf32(0.125f * (na * r * ln_w[2 * lane]));
    g_qn[ob + 1] = to_tf32(0.125f * (nb * r * ln_w[2 * lane + 1]));
}

// ---------------- rope + rmsnorm on K + V copy (table-based) ---------------------
__global__ void kv_process_kernel(const float* __restrict__ ln_w) {
    int idx = blockIdx.x;
    int b = idx >> 9, ks = idx & (KS_ - 1);
    int h = threadIdx.x >> 5;
    int lane = threadIdx.x & 31;
    const float* row = g_kv + (size_t)idx * (2 * D_);
    float a  = row[h * HD_ + 2 * lane];
    float bb = row[h * HD_ + 2 * lane + 1];
    float2 t = g_trig[(ks * STRIDE_) * 32 + lane];
    float na = a * t.x - bb * t.y;
    float nb = a * t.y + bb * t.x;
    float ss = na * na + nb * nb;
#pragma unroll
    for (int o = 16; o; o >>= 1) ss += __shfl_xor_sync(0xffffffffu, ss, o);
    float r = rsqrtf(ss * (1.f / HD_) + EPS_);
    size_t kb = (((size_t)(b * H_ + h) * KS_) + ks) * HD_;
    g_kn[kb + 2 * lane]     = to_tf32(na * r * ln_w[2 * lane]);
    g_kn[kb + 2 * lane + 1] = to_tf32(nb * r * ln_w[2 * lane + 1]);
    g_v[kb + lane]      = to_tf32(row[D_ + h * HD_ + lane]);
    g_v[kb + lane + 32] = to_tf32(row[D_ + h * HD_ + lane + 32]);
}

// ---------------- launcher -------------------------------------------------------
extern "C" void kernel_launch(void* const* d_in, const int* in_sizes, int n_in,
                              void* d_out, int out_size) {
    const float* x       = (const float*)d_in[0];
    const float* rmsq_w  = (const float*)d_in[1];
    const float* q_w     = (const float*)d_in[2];
    const float* q_b     = (const float*)d_in[3];
    const float* rmskv_w = (const float*)d_in[4];
    const float* kv_w    = (const float*)d_in[5];
    const float* kv_b    = (const float*)d_in[6];
    const float* ln_w    = (const float*)d_in[7];
    const float* out_w   = (const float*)d_in[8];
    const float* out_b   = (const float*)d_in[9];
    float* out = (float*)d_out;

    void *p_xqn, *p_xkvn, *p_q, *p_kv, *p_attn, *p_wq, *p_wkv, *p_wo;
    cudaGetSymbolAddress(&p_xqn,  g_xqn);
    cudaGetSymbolAddress(&p_xkvn, g_xkvn);
    cudaGetSymbolAddress(&p_q,    g_q);
    cudaGetSymbolAddress(&p_kv,   g_kv);
    cudaGetSymbolAddress(&p_attn, g_attn);
    cudaGetSymbolAddress(&p_wq,   g_wq);
    cudaGetSymbolAddress(&p_wkv,  g_wkv);
    cudaGetSymbolAddress(&p_wo,   g_wo);

    const int GEMM_SMEM = 109056;   // 3-stage: (3*128*36 + 3*32*140) * 4
    const int ATTN_SMEM = 207104;   // Qs + 3*KV + Ss + sinv
    cudaFuncSetAttribute(gemm_wmma_kernel,
                         cudaFuncAttributeMaxDynamicSharedMemorySize, GEMM_SMEM);
    cudaFuncSetAttribute(attention_wmma_kernel,
                         cudaFuncAttributeMaxDynamicSharedMemorySize, ATTN_SMEM);

    init_base_kernel<<<1, 32>>>();
    trig_kernel<<<C_, 32>>>();
    cvt_kernel<<<(D_*D_/4 + 255)/256, 256>>>(q_w,   (float*)p_wq,  D_*D_/4);
    cvt_kernel<<<(D_*2*D_/4 + 255)/256, 256>>>(kv_w, (float*)p_wkv, D_*2*D_/4);
    cvt_kernel<<<(D_*D_/4 + 255)/256, 256>>>(out_w, (float*)p_wo,  D_*D_/4);
    rmsnorm_dual_kernel<<<B_ * C_, 256>>>(x, rmsq_w, rmskv_w);

    gemm_wmma_kernel<<<dim3(D_ / 128, (B_ * C_) / 128), 256, GEMM_SMEM>>>(
        (const float*)p_xqn, (const float*)p_wq, q_b, (float*)p_q, B_ * C_, D_, D_);

    gemm_wmma_kernel<<<dim3((2 * D_) / 128, (B_ * KS_) / 128), 256, GEMM_SMEM>>>(
        (const float*)p_xkvn, (const float*)p_wkv, kv_b, (float*)p_kv, B_ * KS_, 2 * D_, D_);

    rope_norm_q_kernel<<<B_ * C_, 512>>>(ln_w);
    kv_process_kernel<<<B_ * KS_, 512>>>(ln_w);

    attention_wmma_kernel<<<dim3(C_ / 64, B_ * H_), 512, ATTN_SMEM>>>();

    gemm_wmma_kernel<<<dim3(D_ / 128, (B_ * C_) / 128), 256, GEMM_SMEM>>>(
        (const float*)p_attn, (const float*)p_wo, out_b, out, B_ * C_, D_, D_);
}

// round 7
// speedup vs baseline: 1.0566x; 1.0566x over previous
#include <cuda_runtime.h>
#include <math.h>
#include <stdint.h>
#include <mma.h>

using namespace nvcuda;

#define B_   4
#define C_   2048
#define D_   1024
#define H_   16
#define HD_  64
#define KS_  512
#define STRIDE_ 4
#define EPS_ 1.1920929e-07f

// ---------------- scratch (device globals) -----------------------------------
__device__ float g_xqn [B_*C_*D_];
__device__ float g_xkvn[B_*KS_*D_];
__device__ float g_q   [B_*C_*D_];
__device__ float g_kv  [B_*KS_*2*D_];
__device__ float g_qn  [B_*H_*C_*HD_];    // tf32, pre-scaled by 0.125
__device__ float g_kn  [B_*H_*KS_*HD_];   // tf32
__device__ float g_v   [B_*H_*KS_*HD_];   // tf32
__device__ float g_attn[B_*C_*D_];        // tf32
__device__ float g_wq  [D_*D_];
__device__ float g_wkv [D_*2*D_];
__device__ float g_wo  [D_*D_];
__device__ float g_base[HD_/2];
__device__ float2 g_trig[C_*32];          // (cos, sin) per (t, freq)

__device__ __forceinline__ float to_tf32(float x) {
    float r; asm("cvt.rna.tf32.f32 %0, %1;" : "=f"(r) : "f"(x)); return r;
}
__device__ __forceinline__ uint32_t smem_u32(const void* p) {
    uint32_t a;
    asm("{ .reg .u64 t; cvta.to.shared.u64 t, %1; cvt.u32.u64 %0, t; }"
        : "=r"(a) : "l"(p));
    return a;
}
__device__ __forceinline__ void cp16(uint32_t dst, const void* src) {
    asm volatile("cp.async.cg.shared.global [%0], [%1], 16;" :: "r"(dst), "l"(src));
}
#define CP_COMMIT() asm volatile("cp.async.commit_group;" ::: "memory")
#define CP_WAIT1()  asm volatile("cp.async.wait_group 1;" ::: "memory")
#define CP_WAIT0()  asm volatile("cp.async.wait_group 0;" ::: "memory")

// =================== wmma tf32 GEMM (2-stage cp.async, 2 CTAs/SM) =============
// 128x128 CTA tile, K-chunk 32, 8 warps (2m x 4n), warp tile 64x32.
#define GA_LD 36
#define GB_LD 140
#define EP_LD 36
__global__ __launch_bounds__(256, 2) void gemm_wmma_kernel(
        const float* __restrict__ A, const float* __restrict__ W,
        const float* __restrict__ bias, float* __restrict__ C,
        int M, int N, int K) {
    extern __shared__ float sm[];
    float* As = sm;                       // 2*128*36 = 9216 floats
    float* Bs = sm + 2 * 128 * GA_LD;     // 2*32*140 = 8960 floats
    uint32_t asu = smem_u32(As), bsu = smem_u32(Bs);

    int tid = threadIdx.x;
    int warp = tid >> 5;
    int lane = tid & 31;
    int wm = warp & 1;
    int wn = warp >> 1;
    int m0 = blockIdx.y * 128;
    int n0 = blockIdx.x * 128;
    int nc = K >> 5;

#define G_STAGE(cc, bb) do { \
    uint32_t abase = asu + (uint32_t)(bb) * (128 * GA_LD * 4); \
    _Pragma("unroll") \
    for (int i = 0; i < 4; i++) { \
        int u = tid + i * 256; int r = u >> 3, q = u & 7; \
        cp16(abase + (uint32_t)(r * GA_LD + q * 4) * 4, \
             A + (size_t)(m0 + r) * K + (cc) * 32 + q * 4); \
    } \
    uint32_t bbase = bsu + (uint32_t)(bb) * (32 * GB_LD * 4); \
    _Pragma("unroll") \
    for (int i = 0; i < 4; i++) { \
        int u = tid + i * 256; int r = u >> 5, q = u & 31; \
        cp16(bbase + (uint32_t)(r * GB_LD + q * 4) * 4, \
             W + (size_t)((cc) * 32 + r) * N + n0 + q * 4); \
    } \
    CP_COMMIT(); \
} while (0)

    wmma::fragment<wmma::accumulator, 16, 16, 8, float> acc[4][2];
#pragma unroll
    for (int i = 0; i < 4; i++)
#pragma unroll
        for (int j = 0; j < 2; j++) wmma::fill_fragment(acc[i][j], 0.0f);

    G_STAGE(0, 0);
    G_STAGE(1, 1);

    for (int c = 0; c < nc; c++) {
        if (c + 1 < nc) { CP_WAIT1(); } else { CP_WAIT0(); }
        __syncthreads();
        const float* Ab = As + (c & 1) * (128 * GA_LD);
        const float* Bb = Bs + (c & 1) * (32 * GB_LD);
#pragma unroll
        for (int ks = 0; ks < 4; ks++) {
            wmma::fragment<wmma::matrix_a, 16, 16, 8, wmma::precision::tf32, wmma::row_major> af[4];
            wmma::fragment<wmma::matrix_b, 16, 16, 8, wmma::precision::tf32, wmma::row_major> bf[2];
#pragma unroll
            for (int i = 0; i < 4; i++)
                wmma::load_matrix_sync(af[i], Ab + (wm * 64 + i * 16) * GA_LD + ks * 8, GA_LD);
#pragma unroll
            for (int j = 0; j < 2; j++)
                wmma::load_matrix_sync(bf[j], Bb + (ks * 8) * GB_LD + wn * 32 + j * 16, GB_LD);
#pragma unroll
            for (int i = 0; i < 4; i++)
#pragma unroll
                for (int j = 0; j < 2; j++)
                    wmma::mma_sync(acc[i][j], af[i], bf[j], acc[i][j]);
        }
        __syncthreads();
        if (c + 2 < nc) G_STAGE(c + 2, c & 1);
    }

    float* wsm = sm + warp * (64 * EP_LD);
#pragma unroll
    for (int i = 0; i < 4; i++)
#pragma unroll
        for (int j = 0; j < 2; j++)
            wmma::store_matrix_sync(wsm + (i * 16) * EP_LD + j * 16, acc[i][j], EP_LD,
                                    wmma::mem_row_major);
    __syncwarp();
#pragma unroll
    for (int r2 = 0; r2 < 2; r2++) {
        int r = r2 * 32 + lane;
        float* crow = C + (size_t)(m0 + wm * 64 + r) * N + n0 + wn * 32;
        const float* srow = wsm + r * EP_LD;
        const float* brow = bias + n0 + wn * 32;
#pragma unroll
        for (int q = 0; q < 8; q++) {
            float4 v;
            v.x = srow[q * 4 + 0] + brow[q * 4 + 0];
            v.y = srow[q * 4 + 1] + brow[q * 4 + 1];
            v.z = srow[q * 4 + 2] + brow[q * 4 + 2];
            v.w = srow[q * 4 + 3] + brow[q * 4 + 3];
            *(float4*)(crow + q * 4) = v;
        }
    }
#undef G_STAGE
}

// =================== flash-style wmma attention (110KB smem, 2 CTAs/SM) =======
// block = (bh, 64 q rows); stream 8 chunks of 64 keys; O accum in registers;
// no max-shift (|s| <= 8); 1/sum deferred to epilogue.
#define AQ_LD 72
#define SC_LD 68
__global__ __launch_bounds__(512, 2) void attention_flash_kernel() {
    extern __shared__ float sm[];
    float* Qs   = sm;                      // 64*72        = 4608
    float* KV   = sm + 4608;               // 2*(K+V tile) = 18432
    float* Sch  = sm + 23040;              // 64*68        = 4352
    float* sums = sm + 27392;              // 64
    uint32_t qsu = smem_u32(Qs), kvu = smem_u32(KV);

    int tid = threadIdx.x;
    int warp = tid >> 5;
    int lane = tid & 31;
    int wm = warp & 3;                     // q-tile (16 rows)
    int wn = warp >> 2;                    // k/hd-tile (16 cols)
    int bh = blockIdx.y;
    int qbase = blockIdx.x * 64;

    const float* qsrc = g_qn + ((size_t)bh * C_ + qbase) * HD_;
    const float* ksrc = g_kn + (size_t)bh * KS_ * HD_;
    const float* vsrc = g_v  + (size_t)bh * KS_ * HD_;

#define F_STAGE(ch, bb) do { \
    uint32_t kb = kvu + (uint32_t)(bb) * (9216 * 4); \
    uint32_t vb = kb + 4608 * 4; \
    _Pragma("unroll") \
    for (int i = 0; i < 2; i++) { \
        int u = tid + i * 512; int r = u >> 4, q = u & 15; \
        cp16(kb + (uint32_t)(r * AQ_LD + q * 4) * 4, \
             ksrc + ((ch) * 64 + r) * HD_ + q * 4); \
    } \
    _Pragma("unroll") \
    for (int i = 0; i < 2; i++) { \
        int u = tid + i * 512; int r = u >> 4, q = u & 15; \
        cp16(vb + (uint32_t)(r * AQ_LD + q * 4) * 4, \
             vsrc + ((ch) * 64 + r) * HD_ + q * 4); \
    } \
    CP_COMMIT(); \
} while (0)

    // prologue: Q + chunk0 in group 0, chunk1 in group 1
#pragma unroll
    for (int i = 0; i < 2; i++) {
        int u = tid + i * 512; int r = u >> 4, q = u & 15;
        cp16(qsu + (uint32_t)(r * AQ_LD + q * 4) * 4, qsrc + r * HD_ + q * 4);
    }
    F_STAGE(0, 0);
    F_STAGE(1, 1);

    wmma::fragment<wmma::accumulator, 16, 16, 8, float> oacc;
    wmma::fill_fragment(oacc, 0.0f);
    int r8 = tid >> 3;                     // exp row 0..63
    int c8 = (tid & 7) * 8;                // exp col base

    for (int c = 0; c < 8; c++) {
        if (c == 0) { CP_WAIT1(); } else { CP_WAIT0(); }
        __syncthreads();
        if (c >= 1 && c + 1 < 8) F_STAGE(c + 1, (c + 1) & 1);

        const float* Kb = KV + (c & 1) * 9216;
        const float* Vb = Kb + 4608;

        // scores chunk: S[64][64] = Q @ K_chunk^T (Q pre-scaled by 0.125)
        wmma::fragment<wmma::accumulator, 16, 16, 8, float> sacc;
        wmma::fill_fragment(sacc, 0.0f);
#pragma unroll
        for (int ks = 0; ks < 8; ks++) {
            wmma::fragment<wmma::matrix_a, 16, 16, 8, wmma::precision::tf32, wmma::row_major> af;
            wmma::fragment<wmma::matrix_b, 16, 16, 8, wmma::precision::tf32, wmma::col_major> bf;
            wmma::load_matrix_sync(af, Qs + (wm * 16) * AQ_LD + ks * 8, AQ_LD);
            wmma::load_matrix_sync(bf, Kb + (wn * 16) * AQ_LD + ks * 8, AQ_LD);
            wmma::mma_sync(sacc, af, bf, sacc);
        }
        wmma::store_matrix_sync(Sch + (wm * 16) * SC_LD + wn * 16, sacc, SC_LD,
                                wmma::mem_row_major);
        __syncthreads();

        // exp in place + row-sum accumulation (8 lanes per row)
        {
            float* sp = Sch + r8 * SC_LD + c8;
            float4 v0 = *(float4*)sp;
            float4 v1 = *(float4*)(sp + 4);
            float e0 = __expf(v0.x), e1 = __expf(v0.y), e2 = __expf(v0.z), e3 = __expf(v0.w);
            float e4 = __expf(v1.x), e5 = __expf(v1.y), e6 = __expf(v1.z), e7 = __expf(v1.w);
            float part = ((e0 + e1) + (e2 + e3)) + ((e4 + e5) + (e6 + e7));
            part += __shfl_xor_sync(0xffffffffu, part, 1);
            part += __shfl_xor_sync(0xffffffffu, part, 2);
            part += __shfl_xor_sync(0xffffffffu, part, 4);
            if ((lane & 7) == 0) {
                if (c == 0) sums[r8] = part; else sums[r8] += part;
            }
            float4 w0, w1;
            w0.x = to_tf32(e0); w0.y = to_tf32(e1); w0.z = to_tf32(e2); w0.w = to_tf32(e3);
            w1.x = to_tf32(e4); w1.y = to_tf32(e5); w1.z = to_tf32(e6); w1.w = to_tf32(e7);
            *(float4*)sp = w0;
            *(float4*)(sp + 4) = w1;
        }
        __syncthreads();

        // O += E_chunk @ V_chunk
#pragma unroll
        for (int ks = 0; ks < 8; ks++) {
            wmma::fragment<wmma::matrix_a, 16, 16, 8, wmma::precision::tf32, wmma::row_major> af;
            wmma::fragment<wmma::matrix_b, 16, 16, 8, wmma::precision::tf32, wmma::row_major> bf;
            wmma::load_matrix_sync(af, Sch + (wm * 16) * SC_LD + ks * 8, SC_LD);
            wmma::load_matrix_sync(bf, Vb + (ks * 8) * AQ_LD + wn * 16, AQ_LD);
            wmma::mma_sync(oacc, af, bf, oacc);
        }
    }
    __syncthreads();
    if (tid < 64) sums[tid] = 1.0f / sums[tid];
    wmma::store_matrix_sync(Sch + (wm * 16) * SC_LD + wn * 16, oacc, SC_LD,
                            wmma::mem_row_major);
    __syncthreads();

    int b = bh >> 4, h = bh & 15;
#pragma unroll
    for (int i = 0; i < 2; i++) {
        int u = tid + i * 512;
        int r = u >> 4;
        int q = (u & 15) * 4;
        float s = sums[r];
        const float* src = Sch + r * SC_LD + q;
        float4 w;
        w.x = to_tf32(src[0] * s);
        w.y = to_tf32(src[1] * s);
        w.z = to_tf32(src[2] * s);
        w.w = to_tf32(src[3] * s);
        *(float4*)(g_attn + ((size_t)b * C_ + qbase + r) * D_ + h * HD_ + q) = w;
    }
#undef F_STAGE
}

// ---------------- rope base + trig table ----------------------------------------
__global__ void init_base_kernel() {
    int i = threadIdx.x;
    double end = 2595.0 * log10(21.0);
    double v = (double)i * (end / 31.0);
    double scale = pow(10.0, v / 2595.0) - 1.0;
    g_base[i] = (float)(200.0 * scale / 1000.0);
}
__global__ void trig_kernel() {
    int c = blockIdx.x;
    int lane = threadIdx.x;
    float fr = (float)c * g_base[lane];
    float sn, cs; sincosf(fr, &sn, &cs);
    g_trig[c * 32 + lane] = make_float2(cs, sn);
}

// ---------------- weight tf32 conversion ----------------------------------------
__global__ void cvt_kernel(const float* __restrict__ s, float* __restrict__ d, int n4) {
    int i = blockIdx.x * 256 + threadIdx.x;
    if (i < n4) {
        float4 v = ((const float4*)s)[i];
        v.x = to_tf32(v.x); v.y = to_tf32(v.y);
        v.z = to_tf32(v.z); v.w = to_tf32(v.w);
        ((float4*)d)[i] = v;
    }
}

// ---------------- dual rmsnorm (tf32 outputs) ------------------------------------
__global__ void rmsnorm_dual_kernel(const float* __restrict__ x,
                                    const float* __restrict__ wq,
                                    const float* __restrict__ wkv) {
    int row = blockIdx.x;
    int tid = threadIdx.x;
    const float* xr = x + (size_t)row * D_;
    float v[4]; float ss = 0.f;
#pragma unroll
    for (int i = 0; i < 4; i++) { v[i] = xr[tid + i*256]; ss += v[i]*v[i]; }
#pragma unroll
    for (int o = 16; o; o >>= 1) ss += __shfl_xor_sync(0xffffffffu, ss, o);
    __shared__ float red[8];
    if ((tid & 31) == 0) red[tid >> 5] = ss;
    __syncthreads();
    float tot = 0.f;
#pragma unroll
    for (int i = 0; i < 8; i++) tot += red[i];
    float r = rsqrtf(tot * (1.f / D_) + EPS_);

    int b = row >> 11, c = row & (C_ - 1);
    bool dokv = (c & (STRIDE_ - 1)) == 0;
    int krow = b * KS_ + (c >> 2);
#pragma unroll
    for (int i = 0; i < 4; i++) {
        int col = tid + i*256;
        float n = v[i] * r;
        g_xqn[(size_t)row * D_ + col] = to_tf32(n * wq[col]);
        if (dokv) g_xkvn[(size_t)krow * D_ + col] = to_tf32(n * wkv[col]);
    }
}

// ---------------- rope + per-head rmsnorm on Q (table-based) ---------------------
__global__ void rope_norm_q_kernel(const float* __restrict__ ln_w) {
    int row = blockIdx.x;
    int h = threadIdx.x >> 5;
    int lane = threadIdx.x & 31;
    int b = row >> 11, c = row & (C_ - 1);
    const float* qp = g_q + (size_t)row * D_ + h * HD_;
    float a  = qp[2 * lane];
    float bb = qp[2 * lane + 1];
    float2 t = g_trig[c * 32 + lane];
    float na = a * t.x - bb * t.y;
    float nb = a * t.y + bb * t.x;
    float ss = na * na + nb * nb;
#pragma unroll
    for (int o = 16; o; o >>= 1) ss += __shfl_xor_sync(0xffffffffu, ss, o);
    float r = rsqrtf(ss * (1.f / HD_) + EPS_);
    size_t ob = (((size_t)(b * H_ + h) * C_) + c) * HD_ + 2 * lane;
    g_qn[ob]     = to_tf32(0.125f * (na * r * ln_w[2 * lane]));
    g_qn[ob + 1] = to_tf32(0.125f * (nb * r * ln_w[2 * lane + 1]));
}

// ---------------- rope + rmsnorm on K + V copy (table-based) ---------------------
__global__ void kv_process_kernel(const float* __restrict__ ln_w) {
    int idx = blockIdx.x;
    int b = idx >> 9, ks = idx & (KS_ - 1);
    int h = threadIdx.x >> 5;
    int lane = threadIdx.x & 31;
    const float* row = g_kv + (size_t)idx * (2 * D_);
    float a  = row[h * HD_ + 2 * lane];
    float bb = row[h * HD_ + 2 * lane + 1];
    float2 t = g_trig[(ks * STRIDE_) * 32 + lane];
    float na = a * t.x - bb * t.y;
    float nb = a * t.y + bb * t.x;
    float ss = na * na + nb * nb;
#pragma unroll
    for (int o = 16; o; o >>= 1) ss += __shfl_xor_sync(0xffffffffu, ss, o);
    float r = rsqrtf(ss * (1.f / HD_) + EPS_);
    size_t kb = (((size_t)(b * H_ + h) * KS_) + ks) * HD_;
    g_kn[kb + 2 * lane]     = to_tf32(na * r * ln_w[2 * lane]);
    g_kn[kb + 2 * lane + 1] = to_tf32(nb * r * ln_w[2 * lane + 1]);
    g_v[kb + lane]      = to_tf32(row[D_ + h * HD_ + lane]);
    g_v[kb + lane + 32] = to_tf32(row[D_ + h * HD_ + lane + 32]);
}

// ---------------- launcher -------------------------------------------------------
extern "C" void kernel_launch(void* const* d_in, const int* in_sizes, int n_in,
                              void* d_out, int out_size) {
    const float* x       = (const float*)d_in[0];
    const float* rmsq_w  = (const float*)d_in[1];
    const float* q_w     = (const float*)d_in[2];
    const float* q_b     = (const float*)d_in[3];
    const float* rmskv_w = (const float*)d_in[4];
    const float* kv_w    = (const float*)d_in[5];
    const float* kv_b    = (const float*)d_in[6];
    const float* ln_w    = (const float*)d_in[7];
    const float* out_w   = (const float*)d_in[8];
    const float* out_b   = (const float*)d_in[9];
    float* out = (float*)d_out;

    void *p_xqn, *p_xkvn, *p_q, *p_kv, *p_attn, *p_wq, *p_wkv, *p_wo;
    cudaGetSymbolAddress(&p_xqn,  g_xqn);
    cudaGetSymbolAddress(&p_xkvn, g_xkvn);
    cudaGetSymbolAddress(&p_q,    g_q);
    cudaGetSymbolAddress(&p_kv,   g_kv);
    cudaGetSymbolAddress(&p_attn, g_attn);
    cudaGetSymbolAddress(&p_wq,   g_wq);
    cudaGetSymbolAddress(&p_wkv,  g_wkv);
    cudaGetSymbolAddress(&p_wo,   g_wo);

    const int GEMM_SMEM = 73728;    // 2-stage buffers / epilogue staging
    const int ATTN_SMEM = 109824;   // Qs + 2*(K+V) + Sch + sums
    cudaFuncSetAttribute(gemm_wmma_kernel,
                         cudaFuncAttributeMaxDynamicSharedMemorySize, GEMM_SMEM);
    cudaFuncSetAttribute(attention_flash_kernel,
                         cudaFuncAttributeMaxDynamicSharedMemorySize, ATTN_SMEM);

    init_base_kernel<<<1, 32>>>();
    trig_kernel<<<C_, 32>>>();
    cvt_kernel<<<(D_*D_/4 + 255)/256, 256>>>(q_w,   (float*)p_wq,  D_*D_/4);
    cvt_kernel<<<(D_*2*D_/4 + 255)/256, 256>>>(kv_w, (float*)p_wkv, D_*2*D_/4);
    cvt_kernel<<<(D_*D_/4 + 255)/256, 256>>>(out_w, (float*)p_wo,  D_*D_/4);
    rmsnorm_dual_kernel<<<B_ * C_, 256>>>(x, rmsq_w, rmskv_w);

    gemm_wmma_kernel<<<dim3(D_ / 128, (B_ * C_) / 128), 256, GEMM_SMEM>>>(
        (const float*)p_xqn, (const float*)p_wq, q_b, (float*)p_q, B_ * C_, D_, D_);

    gemm_wmma_kernel<<<dim3((2 * D_) / 128, (B_ * KS_) / 128), 256, GEMM_SMEM>>>(
        (const float*)p_xkvn, (const float*)p_wkv, kv_b, (float*)p_kv, B_ * KS_, 2 * D_, D_);

    rope_norm_q_kernel<<<B_ * C_, 512>>>(ln_w);
    kv_process_kernel<<<B_ * KS_, 512>>>(ln_w);

    attention_flash_kernel<<<dim3(C_ / 64, B_ * H_), 512, ATTN_SMEM>>>();

    gemm_wmma_kernel<<<dim3(D_ / 128, (B_ * C_) / 128), 256, GEMM_SMEM>>>(
        (const float*)p_attn, (const float*)p_wo, out_b, out, B_ * C_, D_, D_);
}

// round 8
// speedup vs baseline: 1.0569x; 1.0003x over previous
#include <cuda_runtime.h>
#include <math.h>
#include <stdint.h>
#include <mma.h>

using namespace nvcuda;

#define B_   4
#define C_   2048
#define D_   1024
#define H_   16
#define HD_  64
#define KS_  512
#define STRIDE_ 4
#define EPS_ 1.1920929e-07f

// ---------------- scratch (device globals) -----------------------------------
__device__ float g_xqn [B_*C_*D_];
__device__ float g_xkvn[B_*KS_*D_];
__device__ float g_q   [B_*C_*D_];
__device__ float g_kv  [B_*KS_*2*D_];
__device__ float g_qn  [B_*H_*C_*HD_];    // tf32, pre-scaled by 0.125
__device__ float g_kn  [B_*H_*KS_*HD_];   // tf32
__device__ float g_v   [B_*H_*KS_*HD_];   // tf32
__device__ float g_attn[B_*C_*D_];        // tf32
__device__ float g_wq  [D_*D_];
__device__ float g_wkv [D_*2*D_];
__device__ float g_wo  [D_*D_];
__device__ float g_base[HD_/2];
__device__ float2 g_trig[C_*32];          // (cos, sin) per (t, freq)

__device__ __forceinline__ float to_tf32(float x) {
    float r; asm("cvt.rna.tf32.f32 %0, %1;" : "=f"(r) : "f"(x)); return r;
}
__device__ __forceinline__ uint32_t smem_u32(const void* p) {
    uint32_t a;
    asm("{ .reg .u64 t; cvta.to.shared.u64 t, %1; cvt.u32.u64 %0, t; }"
        : "=r"(a) : "l"(p));
    return a;
}
__device__ __forceinline__ void cp16(uint32_t dst, const void* src) {
    asm volatile("cp.async.cg.shared.global [%0], [%1], 16;" :: "r"(dst), "l"(src));
}
#define CP_COMMIT() asm volatile("cp.async.commit_group;" ::: "memory")
#define CP_WAIT1()  asm volatile("cp.async.wait_group 1;" ::: "memory")
#define CP_WAIT0()  asm volatile("cp.async.wait_group 0;" ::: "memory")

// =================== wmma tf32 GEMM (2-stage cp.async, 2 CTAs/SM) =============
// 128x128 CTA tile, K-chunk 32, 8 warps (2m x 4n), warp tile 64x32.
#define GA_LD 36
#define GB_LD 140
#define EP_LD 36
__global__ __launch_bounds__(256, 2) void gemm_wmma_kernel(
        const float* __restrict__ A, const float* __restrict__ W,
        const float* __restrict__ bias, float* __restrict__ C,
        int M, int N, int K) {
    extern __shared__ float sm[];
    float* As = sm;                       // 2*128*36 = 9216 floats
    float* Bs = sm + 2 * 128 * GA_LD;     // 2*32*140 = 8960 floats
    uint32_t asu = smem_u32(As), bsu = smem_u32(Bs);

    int tid = threadIdx.x;
    int warp = tid >> 5;
    int lane = tid & 31;
    int wm = warp & 1;
    int wn = warp >> 1;
    int m0 = blockIdx.y * 128;
    int n0 = blockIdx.x * 128;
    int nc = K >> 5;

#define G_STAGE(cc, bb) do { \
    uint32_t abase = asu + (uint32_t)(bb) * (128 * GA_LD * 4); \
    _Pragma("unroll") \
    for (int i = 0; i < 4; i++) { \
        int u = tid + i * 256; int r = u >> 3, q = u & 7; \
        cp16(abase + (uint32_t)(r * GA_LD + q * 4) * 4, \
             A + (size_t)(m0 + r) * K + (cc) * 32 + q * 4); \
    } \
    uint32_t bbase = bsu + (uint32_t)(bb) * (32 * GB_LD * 4); \
    _Pragma("unroll") \
    for (int i = 0; i < 4; i++) { \
        int u = tid + i * 256; int r = u >> 5, q = u & 31; \
        cp16(bbase + (uint32_t)(r * GB_LD + q * 4) * 4, \
             W + (size_t)((cc) * 32 + r) * N + n0 + q * 4); \
    } \
    CP_COMMIT(); \
} while (0)

    wmma::fragment<wmma::accumulator, 16, 16, 8, float> acc[4][2];
#pragma unroll
    for (int i = 0; i < 4; i++)
#pragma unroll
        for (int j = 0; j < 2; j++) wmma::fill_fragment(acc[i][j], 0.0f);

    G_STAGE(0, 0);
    G_STAGE(1, 1);

    for (int c = 0; c < nc; c++) {
        if (c + 1 < nc) { CP_WAIT1(); } else { CP_WAIT0(); }
        __syncthreads();
        const float* Ab = As + (c & 1) * (128 * GA_LD);
        const float* Bb = Bs + (c & 1) * (32 * GB_LD);
#pragma unroll
        for (int ks = 0; ks < 4; ks++) {
            wmma::fragment<wmma::matrix_a, 16, 16, 8, wmma::precision::tf32, wmma::row_major> af[4];
            wmma::fragment<wmma::matrix_b, 16, 16, 8, wmma::precision::tf32, wmma::row_major> bf[2];
#pragma unroll
            for (int i = 0; i < 4; i++)
                wmma::load_matrix_sync(af[i], Ab + (wm * 64 + i * 16) * GA_LD + ks * 8, GA_LD);
#pragma unroll
            for (int j = 0; j < 2; j++)
                wmma::load_matrix_sync(bf[j], Bb + (ks * 8) * GB_LD + wn * 32 + j * 16, GB_LD);
#pragma unroll
            for (int i = 0; i < 4; i++)
#pragma unroll
                for (int j = 0; j < 2; j++)
                    wmma::mma_sync(acc[i][j], af[i], bf[j], acc[i][j]);
        }
        __syncthreads();
        if (c + 2 < nc) G_STAGE(c + 2, c & 1);
    }

    float* wsm = sm + warp * (64 * EP_LD);
#pragma unroll
    for (int i = 0; i < 4; i++)
#pragma unroll
        for (int j = 0; j < 2; j++)
            wmma::store_matrix_sync(wsm + (i * 16) * EP_LD + j * 16, acc[i][j], EP_LD,
                                    wmma::mem_row_major);
    __syncwarp();
#pragma unroll
    for (int r2 = 0; r2 < 2; r2++) {
        int r = r2 * 32 + lane;
        float* crow = C + (size_t)(m0 + wm * 64 + r) * N + n0 + wn * 32;
        const float* srow = wsm + r * EP_LD;
        const float* brow = bias + n0 + wn * 32;
#pragma unroll
        for (int q = 0; q < 8; q++) {
            float4 v;
            v.x = srow[q * 4 + 0] + brow[q * 4 + 0];
            v.y = srow[q * 4 + 1] + brow[q * 4 + 1];
            v.z = srow[q * 4 + 2] + brow[q * 4 + 2];
            v.w = srow[q * 4 + 3] + brow[q * 4 + 3];
            *(float4*)(crow + q * 4) = v;
        }
    }
#undef G_STAGE
}

// =================== flash-style wmma attention (110KB smem, 2 CTAs/SM) =======
// block = (bh, 64 q rows); stream 8 chunks of 64 keys; O accum in registers;
// no max-shift (|s| <= 8); 1/sum deferred to epilogue.
#define AQ_LD 72
#define SC_LD 68
__global__ __launch_bounds__(512, 2) void attention_flash_kernel() {
    extern __shared__ float sm[];
    float* Qs   = sm;                      // 64*72        = 4608
    float* KV   = sm + 4608;               // 2*(K+V tile) = 18432
    float* Sch  = sm + 23040;              // 64*68        = 4352
    float* sums = sm + 27392;              // 64
    uint32_t qsu = smem_u32(Qs), kvu = smem_u32(KV);

    int tid = threadIdx.x;
    int warp = tid >> 5;
    int lane = tid & 31;
    int wm = warp & 3;                     // q-tile (16 rows)
    int wn = warp >> 2;                    // k/hd-tile (16 cols)
    int bh = blockIdx.y;
    int qbase = blockIdx.x * 64;

    const float* qsrc = g_qn + ((size_t)bh * C_ + qbase) * HD_;
    const float* ksrc = g_kn + (size_t)bh * KS_ * HD_;
    const float* vsrc = g_v  + (size_t)bh * KS_ * HD_;

#define F_STAGE(ch, bb) do { \
    uint32_t kb = kvu + (uint32_t)(bb) * (9216 * 4); \
    uint32_t vb = kb + 4608 * 4; \
    _Pragma("unroll") \
    for (int i = 0; i < 2; i++) { \
        int u = tid + i * 512; int r = u >> 4, q = u & 15; \
        cp16(kb + (uint32_t)(r * AQ_LD + q * 4) * 4, \
             ksrc + ((ch) * 64 + r) * HD_ + q * 4); \
    } \
    _Pragma("unroll") \
    for (int i = 0; i < 2; i++) { \
        int u = tid + i * 512; int r = u >> 4, q = u & 15; \
        cp16(vb + (uint32_t)(r * AQ_LD + q * 4) * 4, \
             vsrc + ((ch) * 64 + r) * HD_ + q * 4); \
    } \
    CP_COMMIT(); \
} while (0)

    // prologue: Q + chunk0 in group 0, chunk1 in group 1
#pragma unroll
    for (int i = 0; i < 2; i++) {
        int u = tid + i * 512; int r = u >> 4, q = u & 15;
        cp16(qsu + (uint32_t)(r * AQ_LD + q * 4) * 4, qsrc + r * HD_ + q * 4);
    }
    F_STAGE(0, 0);
    F_STAGE(1, 1);

    wmma::fragment<wmma::accumulator, 16, 16, 8, float> oacc;
    wmma::fill_fragment(oacc, 0.0f);
    int r8 = tid >> 3;                     // exp row 0..63
    int c8 = (tid & 7) * 8;                // exp col base

    for (int c = 0; c < 8; c++) {
        if (c == 0) { CP_WAIT1(); } else { CP_WAIT0(); }
        __syncthreads();
        if (c >= 1 && c + 1 < 8) F_STAGE(c + 1, (c + 1) & 1);

        const float* Kb = KV + (c & 1) * 9216;
        const float* Vb = Kb + 4608;

        // scores chunk: S[64][64] = Q @ K_chunk^T (Q pre-scaled by 0.125)
        wmma::fragment<wmma::accumulator, 16, 16, 8, float> sacc;
        wmma::fill_fragment(sacc, 0.0f);
#pragma unroll
        for (int ks = 0; ks < 8; ks++) {
            wmma::fragment<wmma::matrix_a, 16, 16, 8, wmma::precision::tf32, wmma::row_major> af;
            wmma::fragment<wmma::matrix_b, 16, 16, 8, wmma::precision::tf32, wmma::col_major> bf;
            wmma::load_matrix_sync(af, Qs + (wm * 16) * AQ_LD + ks * 8, AQ_LD);
            wmma::load_matrix_sync(bf, Kb + (wn * 16) * AQ_LD + ks * 8, AQ_LD);
            wmma::mma_sync(sacc, af, bf, sacc);
        }
        wmma::store_matrix_sync(Sch + (wm * 16) * SC_LD + wn * 16, sacc, SC_LD,
                                wmma::mem_row_major);
        __syncthreads();

        // exp in place + row-sum accumulation (8 lanes per row)
        {
            float* sp = Sch + r8 * SC_LD + c8;
            float4 v0 = *(float4*)sp;
            float4 v1 = *(float4*)(sp + 4);
            float e0 = __expf(v0.x), e1 = __expf(v0.y), e2 = __expf(v0.z), e3 = __expf(v0.w);
            float e4 = __expf(v1.x), e5 = __expf(v1.y), e6 = __expf(v1.z), e7 = __expf(v1.w);
            float part = ((e0 + e1) + (e2 + e3)) + ((e4 + e5) + (e6 + e7));
            part += __shfl_xor_sync(0xffffffffu, part, 1);
            part += __shfl_xor_sync(0xffffffffu, part, 2);
            part += __shfl_xor_sync(0xffffffffu, part, 4);
            if ((lane & 7) == 0) {
                if (c == 0) sums[r8] = part; else sums[r8] += part;
            }
            float4 w0, w1;
            w0.x = to_tf32(e0); w0.y = to_tf32(e1); w0.z = to_tf32(e2); w0.w = to_tf32(e3);
            w1.x = to_tf32(e4); w1.y = to_tf32(e5); w1.z = to_tf32(e6); w1.w = to_tf32(e7);
            *(float4*)sp = w0;
            *(float4*)(sp + 4) = w1;
        }
        __syncthreads();

        // O += E_chunk @ V_chunk
#pragma unroll
        for (int ks = 0; ks < 8; ks++) {
            wmma::fragment<wmma::matrix_a, 16, 16, 8, wmma::precision::tf32, wmma::row_major> af;
            wmma::fragment<wmma::matrix_b, 16, 16, 8, wmma::precision::tf32, wmma::row_major> bf;
            wmma::load_matrix_sync(af, Sch + (wm * 16) * SC_LD + ks * 8, SC_LD);
            wmma::load_matrix_sync(bf, Vb + (ks * 8) * AQ_LD + wn * 16, AQ_LD);
            wmma::mma_sync(oacc, af, bf, oacc);
        }
    }
    __syncthreads();
    if (tid < 64) sums[tid] = 1.0f / sums[tid];
    wmma::store_matrix_sync(Sch + (wm * 16) * SC_LD + wn * 16, oacc, SC_LD,
                            wmma::mem_row_major);
    __syncthreads();

    int b = bh >> 4, h = bh & 15;
#pragma unroll
    for (int i = 0; i < 2; i++) {
        int u = tid + i * 512;
        int r = u >> 4;
        int q = (u & 15) * 4;
        float s = sums[r];
        const float* src = Sch + r * SC_LD + q;
        float4 w;
        w.x = to_tf32(src[0] * s);
        w.y = to_tf32(src[1] * s);
        w.z = to_tf32(src[2] * s);
        w.w = to_tf32(src[3] * s);
        *(float4*)(g_attn + ((size_t)b * C_ + qbase + r) * D_ + h * HD_ + q) = w;
    }
#undef F_STAGE
}

// ---------------- rope base + trig table ----------------------------------------
__global__ void init_base_kernel() {
    int i = threadIdx.x;
    double end = 2595.0 * log10(21.0);
    double v = (double)i * (end / 31.0);
    double scale = pow(10.0, v / 2595.0) - 1.0;
    g_base[i] = (float)(200.0 * scale / 1000.0);
}
__global__ void trig_kernel() {
    int c = blockIdx.x;
    int lane = threadIdx.x;
    float fr = (float)c * g_base[lane];
    float sn, cs; sincosf(fr, &sn, &cs);
    g_trig[c * 32 + lane] = make_float2(cs, sn);
}

// ---------------- weight tf32 conversion ----------------------------------------
__global__ void cvt_kernel(const float* __restrict__ s, float* __restrict__ d, int n4) {
    int i = blockIdx.x * 256 + threadIdx.x;
    if (i < n4) {
        float4 v = ((const float4*)s)[i];
        v.x = to_tf32(v.x); v.y = to_tf32(v.y);
        v.z = to_tf32(v.z); v.w = to_tf32(v.w);
        ((float4*)d)[i] = v;
    }
}

// ---------------- dual rmsnorm (tf32 outputs) ------------------------------------
__global__ void rmsnorm_dual_kernel(const float* __restrict__ x,
                                    const float* __restrict__ wq,
                                    const float* __restrict__ wkv) {
    int row = blockIdx.x;
    int tid = threadIdx.x;
    const float* xr = x + (size_t)row * D_;
    float v[4]; float ss = 0.f;
#pragma unroll
    for (int i = 0; i < 4; i++) { v[i] = xr[tid + i*256]; ss += v[i]*v[i]; }
#pragma unroll
    for (int o = 16; o; o >>= 1) ss += __shfl_xor_sync(0xffffffffu, ss, o);
    __shared__ float red[8];
    if ((tid & 31) == 0) red[tid >> 5] = ss;
    __syncthreads();
    float tot = 0.f;
#pragma unroll
    for (int i = 0; i < 8; i++) tot += red[i];
    float r = rsqrtf(tot * (1.f / D_) + EPS_);

    int b = row >> 11, c = row & (C_ - 1);
    bool dokv = (c & (STRIDE_ - 1)) == 0;
    int krow = b * KS_ + (c >> 2);
#pragma unroll
    for (int i = 0; i < 4; i++) {
        int col = tid + i*256;
        float n = v[i] * r;
        g_xqn[(size_t)row * D_ + col] = to_tf32(n * wq[col]);
        if (dokv) g_xkvn[(size_t)krow * D_ + col] = to_tf32(n * wkv[col]);
    }
}

// ---------------- rope + per-head rmsnorm on Q (table-based) ---------------------
__global__ void rope_norm_q_kernel(const float* __restrict__ ln_w) {
    int row = blockIdx.x;
    int h = threadIdx.x >> 5;
    int lane = threadIdx.x & 31;
    int b = row >> 11, c = row & (C_ - 1);
    const float* qp = g_q + (size_t)row * D_ + h * HD_;
    float a  = qp[2 * lane];
    float bb = qp[2 * lane + 1];
    float2 t = g_trig[c * 32 + lane];
    float na = a * t.x - bb * t.y;
    float nb = a * t.y + bb * t.x;
    float ss = na * na + nb * nb;
#pragma unroll
    for (int o = 16; o; o >>= 1) ss += __shfl_xor_sync(0xffffffffu, ss, o);
    float r = rsqrtf(ss * (1.f / HD_) + EPS_);
    size_t ob = (((size_t)(b * H_ + h) * C_) + c) * HD_ + 2 * lane;
    g_qn[ob]     = to_tf32(0.125f * (na * r * ln_w[2 * lane]));
    g_qn[ob + 1] = to_tf32(0.125f * (nb * r * ln_w[2 * lane + 1]));
}

// ---------------- rope + rmsnorm on K + V copy (table-based) ---------------------
__global__ void kv_process_kernel(const float* __restrict__ ln_w) {
    int idx = blockIdx.x;
    int b = idx >> 9, ks = idx & (KS_ - 1);
    int h = threadIdx.x >> 5;
    int lane = threadIdx.x & 31;
    const float* row = g_kv + (size_t)idx * (2 * D_);
    float a  = row[h * HD_ + 2 * lane];
    float bb = row[h * HD_ + 2 * lane + 1];
    float2 t = g_trig[(ks * STRIDE_) * 32 + lane];
    float na = a * t.x - bb * t.y;
    float nb = a * t.y + bb * t.x;
    float ss = na * na + nb * nb;
#pragma unroll
    for (int o = 16; o; o >>= 1) ss += __shfl_xor_sync(0xffffffffu, ss, o);
    float r = rsqrtf(ss * (1.f / HD_) + EPS_);
    size_t kb = (((size_t)(b * H_ + h) * KS_) + ks) * HD_;
    g_kn[kb + 2 * lane]     = to_tf32(na * r * ln_w[2 * lane]);
    g_kn[kb + 2 * lane + 1] = to_tf32(nb * r * ln_w[2 * lane + 1]);
    g_v[kb + lane]      = to_tf32(row[D_ + h * HD_ + lane]);
    g_v[kb + lane + 32] = to_tf32(row[D_ + h * HD_ + lane + 32]);
}

// ---------------- launcher -------------------------------------------------------
extern "C" void kernel_launch(void* const* d_in, const int* in_sizes, int n_in,
                              void* d_out, int out_size) {
    const float* x       = (const float*)d_in[0];
    const float* rmsq_w  = (const float*)d_in[1];
    const float* q_w     = (const float*)d_in[2];
    const float* q_b     = (const float*)d_in[3];
    const float* rmskv_w = (const float*)d_in[4];
    const float* kv_w    = (const float*)d_in[5];
    const float* kv_b    = (const float*)d_in[6];
    const float* ln_w    = (const float*)d_in[7];
    const float* out_w   = (const float*)d_in[8];
    const float* out_b   = (const float*)d_in[9];
    float* out = (float*)d_out;

    void *p_xqn, *p_xkvn, *p_q, *p_kv, *p_attn, *p_wq, *p_wkv, *p_wo;
    cudaGetSymbolAddress(&p_xqn,  g_xqn);
    cudaGetSymbolAddress(&p_xkvn, g_xkvn);
    cudaGetSymbolAddress(&p_q,    g_q);
    cudaGetSymbolAddress(&p_kv,   g_kv);
    cudaGetSymbolAddress(&p_attn, g_attn);
    cudaGetSymbolAddress(&p_wq,   g_wq);
    cudaGetSymbolAddress(&p_wkv,  g_wkv);
    cudaGetSymbolAddress(&p_wo,   g_wo);

    const int GEMM_SMEM = 73728;    // 2-stage buffers / epilogue staging
    const int ATTN_SMEM = 109824;   // Qs + 2*(K+V) + Sch + sums
    cudaFuncSetAttribute(gemm_wmma_kernel,
                         cudaFuncAttributeMaxDynamicSharedMemorySize, GEMM_SMEM);
    cudaFuncSetAttribute(attention_flash_kernel,
                         cudaFuncAttributeMaxDynamicSharedMemorySize, ATTN_SMEM);

    init_base_kernel<<<1, 32>>>();
    trig_kernel<<<C_, 32>>>();
    cvt_kernel<<<(D_*D_/4 + 255)/256, 256>>>(q_w,   (float*)p_wq,  D_*D_/4);
    cvt_kernel<<<(D_*2*D_/4 + 255)/256, 256>>>(kv_w, (float*)p_wkv, D_*2*D_/4);
    cvt_kernel<<<(D_*D_/4 + 255)/256, 256>>>(out_w, (float*)p_wo,  D_*D_/4);
    rmsnorm_dual_kernel<<<B_ * C_, 256>>>(x, rmsq_w, rmskv_w);

    gemm_wmma_kernel<<<dim3(D_ / 128, (B_ * C_) / 128), 256, GEMM_SMEM>>>(
        (const float*)p_xqn, (const float*)p_wq, q_b, (float*)p_q, B_ * C_, D_, D_);

    gemm_wmma_kernel<<<dim3((2 * D_) / 128, (B_ * KS_) / 128), 256, GEMM_SMEM>>>(
        (const float*)p_xkvn, (const float*)p_wkv, kv_b, (float*)p_kv, B_ * KS_, 2 * D_, D_);

    rope_norm_q_kernel<<<B_ * C_, 512>>>(ln_w);
    kv_process_kernel<<<B_ * KS_, 512>>>(ln_w);

    attention_flash_kernel<<<dim3(C_ / 64, B_ * H_), 512, ATTN_SMEM>>>();

    gemm_wmma_kernel<<<dim3(D_ / 128, (B_ * C_) / 128), 256, GEMM_SMEM>>>(
        (const float*)p_attn, (const float*)p_wo, out_b, out, B_ * C_, D_, D_);
}